// round 3
// baseline (speedup 1.0000x reference)
#include <cuda_runtime.h>
#include <math.h>
#include <stdint.h>

// LinearTimeMMDLoss — bulk-async smem-pipelined streaming reduction.
// Pair p: xo=src[2p], xe=src[2p+1], yo=tgt[2p], ye=tgt[2p+1] (rows contiguous!)
// Each block streams contiguous 32KB src + 32KB tgt chunks (8 pairs) through a
// 3-stage cp.async.bulk pipeline; 8 warps compute 1 pair each from smem.

#define D            512
#define D4           (D / 4)            // 128 float4 per row
#define CHUNK_PAIRS  8
#define THREADS      256
#define WARPS        8
#define NSTAGES      3
#define GRID_BLOCKS  148

#define SRC_STAGE_BYTES (CHUNK_PAIRS * 2 * D * 4)   // 32768
#define STAGE_BYTES     (2 * SRC_STAGE_BYTES)       // 65536
#define DYN_SMEM        (NSTAGES * STAGE_BYTES)     // 196608

__device__ double g_block_partials[GRID_BLOCKS];
__device__ int    g_done = 0;

__device__ __forceinline__ uint32_t smem_u32(const void* p) {
    return (uint32_t)__cvta_generic_to_shared(p);
}
__device__ __forceinline__ void mbar_init(uint32_t bar, uint32_t cnt) {
    asm volatile("mbarrier.init.shared::cta.b64 [%0], %1;" :: "r"(bar), "r"(cnt) : "memory");
}
__device__ __forceinline__ void mbar_expect_tx(uint32_t bar, uint32_t bytes) {
    asm volatile("mbarrier.arrive.expect_tx.shared::cta.b64 _, [%0], %1;"
                 :: "r"(bar), "r"(bytes) : "memory");
}
__device__ __forceinline__ void mbar_wait(uint32_t bar, uint32_t parity) {
    asm volatile(
        "{\n\t.reg .pred P;\n\t"
        "WAIT_%=:\n\t"
        "mbarrier.try_wait.parity.shared::cta.b64 P, [%0], %1, 0x989680;\n\t"
        "@P bra DONE_%=;\n\t"
        "bra WAIT_%=;\n\t"
        "DONE_%=:\n\t}"
        :: "r"(bar), "r"(parity) : "memory");
}
__device__ __forceinline__ void bulk_g2s(uint32_t dst, const void* src,
                                         uint32_t bytes, uint32_t bar) {
    asm volatile(
        "cp.async.bulk.shared::cluster.global.mbarrier::complete_tx::bytes "
        "[%0], [%1], %2, [%3];"
        :: "r"(dst), "l"(src), "r"(bytes), "r"(bar) : "memory");
}

// distance accumulation for one lane's 4 float4 strips
__device__ __forceinline__ void accum_dists(
    const float4* __restrict__ xo, const float4* __restrict__ xe,
    const float4* __restrict__ yo, const float4* __restrict__ ye,
    int lane, float& dxx, float& dyy, float& dxy, float& dyx)
{
    #pragma unroll
    for (int k = 0; k < 4; k++) {
        int j = lane + 32 * k;
        float4 a = xo[j], b = xe[j], c = yo[j], e = ye[j];
        float t;
        t = a.x - b.x; dxx = fmaf(t, t, dxx);
        t = a.y - b.y; dxx = fmaf(t, t, dxx);
        t = a.z - b.z; dxx = fmaf(t, t, dxx);
        t = a.w - b.w; dxx = fmaf(t, t, dxx);
        t = c.x - e.x; dyy = fmaf(t, t, dyy);
        t = c.y - e.y; dyy = fmaf(t, t, dyy);
        t = c.z - e.z; dyy = fmaf(t, t, dyy);
        t = c.w - e.w; dyy = fmaf(t, t, dyy);
        t = a.x - e.x; dxy = fmaf(t, t, dxy);
        t = a.y - e.y; dxy = fmaf(t, t, dxy);
        t = a.z - e.z; dxy = fmaf(t, t, dxy);
        t = a.w - e.w; dxy = fmaf(t, t, dxy);
        t = b.x - c.x; dyx = fmaf(t, t, dyx);
        t = b.y - c.y; dyx = fmaf(t, t, dyx);
        t = b.z - c.z; dyx = fmaf(t, t, dyx);
        t = b.w - c.w; dyx = fmaf(t, t, dyx);
    }
}

__device__ __forceinline__ double pair_h(float dxx, float dyy, float dxy, float dyx)
{
    float bw = (dxx + dyy + dxy + dyx) * (0.25f * 0.25f); // /4 then /2^(5//2)=/4
    double h = 0.0;
    float mult = 1.0f;
    #pragma unroll
    for (int k = 0; k < 5; k++) {
        float b  = bw * mult + 1e-6f;
        float ib = 1.0f / b;
        h += (double)expf(-dxx * ib) + (double)expf(-dyy * ib)
           - (double)expf(-dxy * ib) - (double)expf(-dyx * ib);
        mult *= 2.0f;
    }
    return h;
}

extern __shared__ char smem_dyn[];

__global__ void __launch_bounds__(THREADS) mmd_pipe_kernel(
    const float* __restrict__ src,
    const float* __restrict__ tgt,
    float* __restrict__ out,
    int m2, int nblocks)
{
    __shared__ uint64_t mbar_store[NSTAGES];
    __shared__ double   s_warp[WARPS];
    __shared__ bool     s_last;

    const int tid  = threadIdx.x;
    const int w    = tid >> 5;
    const int lane = tid & 31;
    const int bid  = blockIdx.x;

    uint32_t bar0 = smem_u32(&mbar_store[0]);

    if (tid == 0) {
        #pragma unroll
        for (int s = 0; s < NSTAGES; s++) mbar_init(bar0 + 8u * s, 1);
        asm volatile("fence.proxy.async.shared::cta;" ::: "memory");
    }
    __syncthreads();

    const int nchunks = m2 / CHUNK_PAIRS;

    // prologue: prefetch up to NSTAGES chunks
    if (tid == 0) {
        #pragma unroll
        for (int s = 0; s < NSTAGES; s++) {
            int c = bid + s * nblocks;
            if (c < nchunks) {
                uint32_t sdst = smem_u32(smem_dyn) + (uint32_t)(s * STAGE_BYTES);
                mbar_expect_tx(bar0 + 8u * s, STAGE_BYTES);
                bulk_g2s(sdst,                   src + (size_t)c * (CHUNK_PAIRS * 2 * D),
                         SRC_STAGE_BYTES, bar0 + 8u * s);
                bulk_g2s(sdst + SRC_STAGE_BYTES, tgt + (size_t)c * (CHUNK_PAIRS * 2 * D),
                         SRC_STAGE_BYTES, bar0 + 8u * s);
            }
        }
    }

    double h_acc = 0.0;
    int it = 0;
    for (int c = bid; c < nchunks; c += nblocks, it++) {
        const int st     = it % NSTAGES;
        const int parity = (it / NSTAGES) & 1;
        mbar_wait(bar0 + 8u * st, parity);

        const float4* sbuf = (const float4*)(smem_dyn + (size_t)st * STAGE_BYTES);
        const float4* tbuf = sbuf + SRC_STAGE_BYTES / 16;
        const float4* xo = sbuf + w * (2 * D4);
        const float4* xe = xo + D4;
        const float4* yo = tbuf + w * (2 * D4);
        const float4* ye = yo + D4;

        float dxx = 0.f, dyy = 0.f, dxy = 0.f, dyx = 0.f;
        accum_dists(xo, xe, yo, ye, lane, dxx, dyy, dxy, dyx);

        #pragma unroll
        for (int off = 16; off > 0; off >>= 1) {
            dxx += __shfl_xor_sync(0xffffffffu, dxx, off);
            dyy += __shfl_xor_sync(0xffffffffu, dyy, off);
            dxy += __shfl_xor_sync(0xffffffffu, dxy, off);
            dyx += __shfl_xor_sync(0xffffffffu, dyx, off);
        }
        if (lane == 0) h_acc += pair_h(dxx, dyy, dxy, dyx);

        __syncthreads();   // everyone done reading stage st

        if (tid == 0) {
            int cn = c + NSTAGES * nblocks;
            if (cn < nchunks) {
                uint32_t sdst = smem_u32(smem_dyn) + (uint32_t)(st * STAGE_BYTES);
                mbar_expect_tx(bar0 + 8u * st, STAGE_BYTES);
                bulk_g2s(sdst,                   src + (size_t)cn * (CHUNK_PAIRS * 2 * D),
                         SRC_STAGE_BYTES, bar0 + 8u * st);
                bulk_g2s(sdst + SRC_STAGE_BYTES, tgt + (size_t)cn * (CHUNK_PAIRS * 2 * D),
                         SRC_STAGE_BYTES, bar0 + 8u * st);
            }
        }
    }

    // tail pairs (if m2 not a multiple of CHUNK_PAIRS) — block 0, direct LDG
    if (bid == 0) {
        for (int p = nchunks * CHUNK_PAIRS + w; p < m2; p += WARPS) {
            const float4* xo = (const float4*)(src + (size_t)(2 * p)     * D);
            const float4* xe = (const float4*)(src + (size_t)(2 * p + 1) * D);
            const float4* yo = (const float4*)(tgt + (size_t)(2 * p)     * D);
            const float4* ye = (const float4*)(tgt + (size_t)(2 * p + 1) * D);
            float dxx = 0.f, dyy = 0.f, dxy = 0.f, dyx = 0.f;
            accum_dists(xo, xe, yo, ye, lane, dxx, dyy, dxy, dyx);
            #pragma unroll
            for (int off = 16; off > 0; off >>= 1) {
                dxx += __shfl_xor_sync(0xffffffffu, dxx, off);
                dyy += __shfl_xor_sync(0xffffffffu, dyy, off);
                dxy += __shfl_xor_sync(0xffffffffu, dxy, off);
                dyx += __shfl_xor_sync(0xffffffffu, dyx, off);
            }
            if (lane == 0) h_acc += pair_h(dxx, dyy, dxy, dyx);
        }
    }

    // block partial
    if (lane == 0) s_warp[w] = h_acc;
    __syncthreads();
    if (tid == 0) {
        double sum = 0.0;
        #pragma unroll
        for (int i = 0; i < WARPS; i++) sum += s_warp[i];
        g_block_partials[bid] = sum;
        __threadfence();
        int prev = atomicAdd(&g_done, 1);
        s_last = (prev == nblocks - 1);
    }
    __syncthreads();

    if (s_last) {
        __shared__ double s_r[THREADS];
        double v = 0.0;
        for (int i = tid; i < nblocks; i += THREADS)
            v += g_block_partials[i];
        s_r[tid] = v;
        __syncthreads();
        #pragma unroll
        for (int off = THREADS / 2; off > 0; off >>= 1) {
            if (tid < off) s_r[tid] += s_r[tid + off];
            __syncthreads();
        }
        if (tid == 0) {
            out[0] = (float)(s_r[0] / (double)m2);
            g_done = 0;               // reset for next graph replay
            __threadfence();
        }
    }
}

extern "C" void kernel_launch(void* const* d_in, const int* in_sizes, int n_in,
                              void* d_out, int out_size)
{
    const float* source = (const float*)d_in[0];
    const float* target = (const float*)d_in[1];
    float* out = (float*)d_out;

    const int m  = in_sizes[0] / D;   // 65536
    const int m2 = m / 2;             // 32768

    static int attr_set = 0;          // idempotent host-side attribute set
    if (!attr_set) {
        cudaFuncSetAttribute(mmd_pipe_kernel,
                             cudaFuncAttributeMaxDynamicSharedMemorySize, DYN_SMEM);
        attr_set = 1;
    }

    int nchunks = m2 / CHUNK_PAIRS;
    int nblocks = GRID_BLOCKS;
    if (nchunks < nblocks) nblocks = (nchunks > 0) ? nchunks : 1;

    mmd_pipe_kernel<<<nblocks, THREADS, DYN_SMEM>>>(source, target, out, m2, nblocks);
}

// round 4
// speedup vs baseline: 1.1138x; 1.1138x over previous
#include <cuda_runtime.h>
#include <math.h>

// LinearTimeMMDLoss — single fused kernel, 1 pair per warp, front-batched loads.
// Key fix vs R2: __launch_bounds__(256, 2) grants ptxas ~128 regs so the 16
// float4 loads (64 regs) can ALL be in flight (MLP_p1=16) instead of being
// re-serialized at the 48-reg default.

#define D 512
#define D4 (D / 4)                 // 128 float4 per row
#define WARPS_PER_BLOCK 8
#define THREADS (WARPS_PER_BLOCK * 32)
#define MAX_BLOCKS 4096

__device__ double g_block_partials[MAX_BLOCKS];
__device__ int    g_done = 0;     // reset by last block each call (graph-safe)

__global__ void __launch_bounds__(THREADS, 2) mmd_kernel(
    const float* __restrict__ source,
    const float* __restrict__ target,
    float* __restrict__ out,
    int m2, int num_blocks)
{
    const int warp_id = threadIdx.x >> 5;
    const int lane    = threadIdx.x & 31;
    const int pair    = blockIdx.x * WARPS_PER_BLOCK + warp_id;

    double h = 0.0;

    if (pair < m2) {
        const float4* __restrict__ xo =
            (const float4*)(source + (size_t)(2 * pair) * D) + lane;
        const float4* __restrict__ xe = xo + D4;
        const float4* __restrict__ yo =
            (const float4*)(target + (size_t)(2 * pair) * D) + lane;
        const float4* __restrict__ ye = yo + D4;

        // ---- front-batch ALL 16 independent float4 loads ----
        float4 A0 = xo[0],  A1 = xo[32],  A2 = xo[64],  A3 = xo[96];
        float4 B0 = xe[0],  B1 = xe[32],  B2 = xe[64],  B3 = xe[96];
        float4 C0 = yo[0],  C1 = yo[32],  C2 = yo[64],  C3 = yo[96];
        float4 E0 = ye[0],  E1 = ye[32],  E2 = ye[64],  E3 = ye[96];

        float dxx = 0.f, dyy = 0.f, dxy = 0.f, dyx = 0.f;
        float t;

        #define ACC4(a, b, acc) \
            t = a.x - b.x; acc = fmaf(t, t, acc); \
            t = a.y - b.y; acc = fmaf(t, t, acc); \
            t = a.z - b.z; acc = fmaf(t, t, acc); \
            t = a.w - b.w; acc = fmaf(t, t, acc);

        ACC4(A0, B0, dxx)  ACC4(A1, B1, dxx)  ACC4(A2, B2, dxx)  ACC4(A3, B3, dxx)
        ACC4(C0, E0, dyy)  ACC4(C1, E1, dyy)  ACC4(C2, E2, dyy)  ACC4(C3, E3, dyy)
        ACC4(A0, E0, dxy)  ACC4(A1, E1, dxy)  ACC4(A2, E2, dxy)  ACC4(A3, E3, dxy)
        ACC4(B0, C0, dyx)  ACC4(B1, C1, dyx)  ACC4(B2, C2, dyx)  ACC4(B3, C3, dyx)
        #undef ACC4

        // warp tree-reduce the four sums (deterministic)
        #pragma unroll
        for (int off = 16; off > 0; off >>= 1) {
            dxx += __shfl_xor_sync(0xffffffffu, dxx, off);
            dyy += __shfl_xor_sync(0xffffffffu, dyy, off);
            dxy += __shfl_xor_sync(0xffffffffu, dxy, off);
            dyx += __shfl_xor_sync(0xffffffffu, dyx, off);
        }

        if (lane == 0) {
            float bw = (dxx + dyy + dxy + dyx) * (0.25f * 0.25f);
            float mult = 1.0f;
            #pragma unroll
            for (int k = 0; k < 5; k++) {
                float b  = bw * mult + 1e-6f;
                float ib = 1.0f / b;
                h += (double)expf(-dxx * ib) + (double)expf(-dyy * ib)
                   - (double)expf(-dxy * ib) - (double)expf(-dyx * ib);
                mult *= 2.0f;
            }
        }
    }

    // ---- block partial (lane 0 of each warp holds h) ----
    __shared__ double s_h[WARPS_PER_BLOCK];
    __shared__ bool   s_last;
    if (lane == 0) s_h[warp_id] = h;
    __syncthreads();

    if (threadIdx.x == 0) {
        double sum = 0.0;
        #pragma unroll
        for (int w = 0; w < WARPS_PER_BLOCK; w++) sum += s_h[w];
        g_block_partials[blockIdx.x] = sum;
        __threadfence();
        int prev = atomicAdd(&g_done, 1);
        s_last = (prev == num_blocks - 1);
    }
    __syncthreads();

    if (s_last) {
        __shared__ double s_r[THREADS];
        double v = 0.0;
        for (int i = threadIdx.x; i < num_blocks; i += THREADS)
            v += g_block_partials[i];
        s_r[threadIdx.x] = v;
        __syncthreads();
        #pragma unroll
        for (int off = THREADS / 2; off > 0; off >>= 1) {
            if (threadIdx.x < off) s_r[threadIdx.x] += s_r[threadIdx.x + off];
            __syncthreads();
        }
        if (threadIdx.x == 0) {
            out[0] = (float)(s_r[0] / (double)m2);
            g_done = 0;               // reset for next graph replay
            __threadfence();
        }
    }
}

extern "C" void kernel_launch(void* const* d_in, const int* in_sizes, int n_in,
                              void* d_out, int out_size)
{
    const float* source = (const float*)d_in[0];
    const float* target = (const float*)d_in[1];
    float* out = (float*)d_out;

    const int m  = in_sizes[0] / D;   // 65536
    const int m2 = m / 2;             // 32768

    int blocks = (m2 + WARPS_PER_BLOCK - 1) / WARPS_PER_BLOCK;  // 4096
    if (blocks > MAX_BLOCKS) blocks = MAX_BLOCKS;

    mmd_kernel<<<blocks, THREADS>>>(source, target, out, m2, blocks);
}